// round 10
// baseline (speedup 1.0000x reference)
#include <cuda_runtime.h>

// Projection: per row i of x[N,128]:
//   sq = sum(x_i^2); s = (sq-1)/(sq+1); out_i = [(1-s)*x_i, s]  -> out[N,129]
// with (1-s) = 2/(1+sq).
//
// HBM-bound streaming, converged near the mixed r/w wall.
// Evidence: R1 stores merge in L2 (traffic==payload); R2 smem staging -18%;
// R3 scalar ldcs 4 rows/warp best base; R4 8 rows/warp neutral (default
// stores); R9 __stcs stores +1.6% DRAM (6.74TB/s, 156.2us) — best.
// R10 A/B: 8 rows/warp x __stcs interaction — longer contiguous dirty spans
// per warp for the LTS write-back scheduler, half the tail-store overhead.

#define D 128
#define THREADS 256
#define WARPS (THREADS / 32)
#define ROWS_PER_WARP 8
#define ROWS_PER_BLOCK (WARPS * ROWS_PER_WARP)   // 64

__global__ void __launch_bounds__(THREADS) projection_kernel(
    const float* __restrict__ x, float* __restrict__ out)
{
    const int warp = threadIdx.x >> 5;
    const int lane = threadIdx.x & 31;
    const long long row0 = (long long)blockIdx.x * ROWS_PER_BLOCK
                         + (long long)warp * ROWS_PER_WARP;

    const float* __restrict__ xr = x + row0 * D + lane;

    // Front-batched, fully coalesced streaming loads: 32 x LDG.32.CS
    float v[ROWS_PER_WARP][4];
    #pragma unroll
    for (int r = 0; r < ROWS_PER_WARP; r++)
        #pragma unroll
        for (int c = 0; c < 4; c++)
            v[r][c] = __ldcs(xr + r * D + c * 32);

    float sq[ROWS_PER_WARP];
    #pragma unroll
    for (int r = 0; r < ROWS_PER_WARP; r++)
        sq[r] = v[r][0] * v[r][0] + v[r][1] * v[r][1]
              + v[r][2] * v[r][2] + v[r][3] * v[r][3];

    // Interleaved warp reductions; afterwards every lane holds all sq[r]
    #pragma unroll
    for (int off = 16; off > 0; off >>= 1)
        #pragma unroll
        for (int r = 0; r < ROWS_PER_WARP; r++)
            sq[r] += __shfl_xor_sync(0xFFFFFFFFu, sq[r], off);

    #pragma unroll
    for (int r = 0; r < ROWS_PER_WARP; r++) {
        const float inv   = 1.0f / (1.0f + sq[r]);
        const float scale = 2.0f * inv;        // = 1 - s

        float* __restrict__ orow = out + (row0 + r) * (D + 1);
        #pragma unroll
        for (int c = 0; c < 4; c++)
            __stcs(orow + lane + c * 32, scale * v[r][c]);
    }

    // Tail scalars: lane r stores s for row (row0 + r) — one STG, 8 active lanes.
    if (lane < ROWS_PER_WARP) {
        const float sql = sq[lane];
        __stcs(out + (row0 + lane) * (D + 1) + D, (sql - 1.0f) / (1.0f + sql));
    }
}

extern "C" void kernel_launch(void* const* d_in, const int* in_sizes, int n_in,
                              void* d_out, int out_size)
{
    const float* x = (const float*)d_in[0];
    float* out = (float*)d_out;
    const int n_rows = in_sizes[0] / D;                    // 1048576
    const int blocks = n_rows / ROWS_PER_BLOCK;            // exact: 16384
    projection_kernel<<<blocks, THREADS>>>(x, out);
}